// round 14
// baseline (speedup 1.0000x reference)
#include <cuda_runtime.h>
#include <cuda_bf16.h>
#include <stdint.h>
#include <math.h>

#define VOCAB 32000
#define HID   512
#define EMB   256
#define NB    256
#define LEN   512

#define CL    8            // h-tile CTAs per group
#define NGRP  32           // groups (chains) of 8 batch rows
#define RPG   8            // rows per group
#define GRID  128
#define NTHR  512

typedef unsigned long long u64;

// Scratch (static device allocations are allowed; runtime allocs are not).
__device__ float g_P[VOCAB * HID];            // P = emb @ Wxh^T + b  (65.5 MB)
__device__ float g_h[2][NB * HID];            // ping-pong hidden state
__device__ unsigned g_flag[NGRP * CL * 64];   // per-(group,producer) flags, 256B apart
__device__ unsigned g_cnt[64];                // end-of-kernel cleanup counter

// Packed fp32x2 ops (B300 packed pipe; ptxas never emits these from C++).
__device__ __forceinline__ u64 ffma2(u64 a, u64 b, u64 c) {
    u64 d;
    asm("fma.rn.f32x2 %0, %1, %2, %3;" : "=l"(d) : "l"(a), "l"(b), "l"(c));
    return d;
}

// ---------------------------------------------------------------------------
// proj_kernel: g_P[v,h] = sum_e emb[v,e] * Wxh_w[h,e] + Wxh_b[h]   (FFMA2)
// ---------------------------------------------------------------------------
__global__ void proj_kernel(const float* __restrict__ emb,
                            const float* __restrict__ Wxh_w,
                            const float* __restrict__ Wxh_b) {
    const int K   = EMB;
    const int STR = EMB + 4;
    extern __shared__ float sm[];
    float* As  = sm;
    float* Ws  = sm + 32 * STR;
    float* red = sm + 64 * STR;

    const int tid = threadIdx.x;
    const int v0  = blockIdx.x * 32;
    const int h0  = blockIdx.y * 32;

    const int NV4 = 32 * (K / 4);
    for (int idx = tid; idx < NV4; idx += 256) {
        int r  = idx / (K / 4);
        int c4 = (idx % (K / 4)) * 4;
        *(float4*)&As[r * STR + c4] = *(const float4*)&emb[(size_t)(v0 + r) * K + c4];
        *(float4*)&Ws[r * STR + c4] = *(const float4*)&Wxh_w[(size_t)(h0 + r) * K + c4];
    }
    __syncthreads();

    const int lane = tid & 31, kg = tid >> 5;
    const int ln = lane & 7, lh = lane >> 3;
    const int kb = kg * (K / 8);

    u64 acc[4][8];
#pragma unroll
    for (int i = 0; i < 4; i++)
#pragma unroll
        for (int j = 0; j < 8; j++) acc[i][j] = 0ULL;

#pragma unroll 4
    for (int kk = 0; kk < K / 8; kk += 4) {
        float4 av[4], wv[8];
#pragma unroll
        for (int i = 0; i < 4; i++)
            av[i] = *(const float4*)&As[(ln + 8 * i) * STR + kb + kk];
#pragma unroll
        for (int j = 0; j < 8; j++)
            wv[j] = *(const float4*)&Ws[(lh + 4 * j) * STR + kb + kk];
#pragma unroll
        for (int i = 0; i < 4; i++) {
            u64 alo = ((const u64*)&av[i])[0], ahi = ((const u64*)&av[i])[1];
#pragma unroll
            for (int j = 0; j < 8; j++) {
                u64 wlo = ((const u64*)&wv[j])[0], whi = ((const u64*)&wv[j])[1];
                acc[i][j] = ffma2(alo, wlo, acc[i][j]);
                acc[i][j] = ffma2(ahi, whi, acc[i][j]);
            }
        }
    }

#pragma unroll
    for (int i = 0; i < 4; i++)
#pragma unroll
        for (int j = 0; j < 8; j++) {
            float2 f = *(float2*)&acc[i][j];
            red[kg * 1152 + (ln + 8 * i) * 36 + (lh + 4 * j)] = f.x + f.y;
        }
    __syncthreads();

    const int o_n = tid >> 3, o_h = (tid & 7) * 4;
    float4 s = make_float4(0.f, 0.f, 0.f, 0.f);
#pragma unroll
    for (int g = 0; g < 8; g++) {
        float4 p = *(const float4*)&red[g * 1152 + o_n * 36 + o_h];
        s.x += p.x; s.y += p.y; s.z += p.z; s.w += p.w;
    }
    float4 b4 = *(const float4*)&Wxh_b[h0 + o_h];
    s.x += b4.x; s.y += b4.y; s.z += b4.z; s.w += b4.w;
    *(float4*)&g_P[(size_t)(v0 + o_n) * HID + h0 + o_h] = s;
}

// ---------------------------------------------------------------------------
// rnn_kernel: persistent, dual-chain software-pipelined. NO clusters.
//   128 CTAs; CTA (q = bid>>3, j = bid&7) serves TWO independent chains:
//   chain A = group 2q (rows q*16..+8), chain B = group 2q+1 (rows q*16+8..+8),
//   both with h-block j (64 h cols) and shared weight registers.
//   Per-iteration schedule (step t for both chains):
//     waitA-data -> computeA -> [pollB + loadB] -> sync
//     -> reduceA/epilogueA/prefetch -> sync -> publishA
//     -> waitB-data -> computeB -> sync
//     -> reduceB/epilogueB/prefetch -> sync -> publishB
//     -> [pollA(t+1) + loadA]
//   Every poll trails its producers' publish by >= one compute phase, and
//   every cp.async flies under another phase's work.
// ---------------------------------------------------------------------------
__global__ void __launch_bounds__(NTHR, 1)
rnn_kernel(const int*   __restrict__ X,
           const float* __restrict__ Whh_w,
           const float* __restrict__ Whh_b,
           float*       __restrict__ out)
{
    extern __shared__ float sm[];
    float* sm_hA   = sm;             // [16 w][8 n][32 k]  16 KB
    float* sm_hB   = sm + 4096;      // 16 KB
    float* sm_redA = sm + 8192;      // [16 g][8 n][64 h]  32 KB
    float* sm_redB = sm + 16384;     // 32 KB

    const int tid   = threadIdx.x;
    const int w     = tid >> 5;
    const int lane  = tid & 31;
    const int q     = blockIdx.x >> 3;
    const int j_own = blockIdx.x & 7;
    const int gA    = 2 * q, gB = 2 * q + 1;
    const int n0A   = q * 16;
    const int n0B   = q * 16 + 8;
    const int h0    = j_own * 64;
    const int hA    = h0 + 2 * lane;

    const int  j_src   = w >> 1;
    const bool is_self = (j_src == j_own);

    // --- persistent weight registers: rows hA,hA+1, k in [32w, 32w+32) -----
    u64 wAr[16], wBr[16];
    {
        const u64* pa = (const u64*)&Whh_w[(size_t)hA * HID + w * 32];
        const u64* pb = (const u64*)&Whh_w[(size_t)(hA + 1) * HID + w * 32];
#pragma unroll
        for (int i = 0; i < 16; i++) { wAr[i] = pa[i]; wBr[i] = pb[i]; }
    }

    unsigned int baseA, baseB;
    {
        unsigned int a, b;
        asm("{ .reg .u64 t; cvta.to.shared.u64 t, %1; cvt.u32.u64 %0, t; }"
            : "=r"(a) : "l"(sm_hA + w * 256));
        asm("{ .reg .u64 t; cvta.to.shared.u64 t, %1; cvt.u32.u64 %0, t; }"
            : "=r"(b) : "l"(sm_hB + w * 256));
        baseA = a; baseB = b;
    }

    // epilogue ownership: thread -> (row n0?+en, single col h0+eh)
    const int   en   = tid >> 6;          // 0..7
    const int   eh   = tid & 63;          // 0..63
    const int   rowA = n0A + en;
    const int   rowB = n0B + en;
    const float eb   = Whh_b[h0 + eh];
    float* selfA = &sm_hA[(2 * j_own + (eh >> 5)) * 256 + en * 32 + (eh & 31)];
    float* selfB = &sm_hB[(2 * j_own + (eh >> 5)) * 256 + en * 32 + (eh & 31)];

    unsigned* fA_my  = &g_flag[(gA * CL + j_own) * 64];
    unsigned* fB_my  = &g_flag[(gB * CL + j_own) * 64];
    unsigned* fA_src = &g_flag[(gA * CL + j_src) * 64];
    unsigned* fB_src = &g_flag[(gB * CL + j_src) * 64];

    // ======================= step 0: h0 == 0 ================================
    float pA, pB;
    {
        int xa = __ldg(&X[rowA * LEN]);
        int xb = __ldg(&X[rowB * LEN]);
        pA = __ldg(&g_P[(size_t)xa * HID + h0 + eh]);
        pB = __ldg(&g_P[(size_t)xb * HID + h0 + eh]);
    }
    {
        float oA = tanhf(eb + pA), oB = tanhf(eb + pB);
        g_h[0][(size_t)rowA * HID + h0 + eh] = oA;  *selfA = oA;
        g_h[0][(size_t)rowB * HID + h0 + eh] = oB;  *selfB = oB;
    }
    // prefetch t=1 gathers
    {
        int xa = __ldg(&X[rowA * LEN + 1]);
        int xb = __ldg(&X[rowB * LEN + 1]);
        pA = __ldg(&g_P[(size_t)xa * HID + h0 + eh]);
        pB = __ldg(&g_P[(size_t)xb * HID + h0 + eh]);
    }
    __syncthreads();
    if (tid == 0) {
        asm volatile("st.release.gpu.u32 [%0], %1;" :: "l"(fA_my), "r"(1u) : "memory");
        asm volatile("st.release.gpu.u32 [%0], %1;" :: "l"(fB_my), "r"(1u) : "memory");
    }
    // pre-commit A(1) load
    if (!is_self) {
        if (lane == 0) {
            unsigned g;
            do {
                asm volatile("ld.acquire.gpu.u32 %0, [%1];"
                             : "=r"(g) : "l"(fA_src) : "memory");
            } while (g < 1u);
        }
        __syncwarp();
#pragma unroll
        for (int i = 0; i < 2; i++) {
            int c = i * 32 + lane;           // 0..63 ; n=c>>3, kq=c&7
            const float* src = &g_h[0][(size_t)(n0A + (c >> 3)) * HID + w * 32 + (c & 7) * 4];
            asm volatile("cp.async.cg.shared.global [%0], [%1], 16;"
                         :: "r"(baseA + c * 16), "l"(src) : "memory");
        }
        asm volatile("cp.async.commit_group;" ::: "memory");
    }

    // ======================= main loop ======================================
    for (int t = 1; t < LEN; t++) {
        const float* hin = g_h[(t - 1) & 1];
        float* dst = (t == LEN - 1) ? out : g_h[t & 1];
        const bool more = (t < LEN - 1);

        // ---- Phase 1-2: chain A compute --------------------------------
        if (!is_self)
            asm volatile("cp.async.wait_group 0;" ::: "memory");
        {
            u64 aA[8], aB[8];
#pragma unroll
            for (int n = 0; n < 8; n++) { aA[n] = 0ULL; aB[n] = 0ULL; }
            const float* hp = sm_hA + w * 256;
#pragma unroll
            for (int n = 0; n < 8; n++) {
                const float4* row = (const float4*)(hp + n * 32);
                u64 a0 = aA[n], a1 = aB[n];
#pragma unroll
                for (int j = 0; j < 8; j++) {
                    float4 hv = row[j];
                    u64 lo = ((const u64*)&hv)[0];
                    u64 hi = ((const u64*)&hv)[1];
                    a0 = ffma2(lo, wAr[2 * j],     a0);
                    a0 = ffma2(hi, wAr[2 * j + 1], a0);
                    a1 = ffma2(lo, wBr[2 * j],     a1);
                    a1 = ffma2(hi, wBr[2 * j + 1], a1);
                }
                aA[n] = a0; aB[n] = a1;
            }
#pragma unroll
            for (int n = 0; n < 8; n++) {
                float2 fa = *(float2*)&aA[n];
                float2 fb = *(float2*)&aB[n];
                *(float2*)&sm_redA[w * 512 + n * 64 + 2 * lane] =
                    make_float2(fa.x + fa.y, fb.x + fb.y);
            }
        }

        // ---- Phase 3: chain B poll + load (published last iteration) ---
        if (!is_self) {
            if (lane == 0) {
                unsigned g;
                do {
                    asm volatile("ld.acquire.gpu.u32 %0, [%1];"
                                 : "=r"(g) : "l"(fB_src) : "memory");
                } while (g < (unsigned)t);
            }
            __syncwarp();
#pragma unroll
            for (int i = 0; i < 2; i++) {
                int c = i * 32 + lane;
                const float* src = &hin[(size_t)(n0B + (c >> 3)) * HID + w * 32 + (c & 7) * 4];
                asm volatile("cp.async.cg.shared.global [%0], [%1], 16;"
                             :: "r"(baseB + c * 16), "l"(src) : "memory");
            }
            asm volatile("cp.async.commit_group;" ::: "memory");
        }
        __syncthreads();

        // ---- Phase 4-6: reduce A, epilogue A, publish A ----------------
        {
            float s0 = 0.f, s1 = 0.f;
#pragma unroll
            for (int g = 0; g < 16; g += 2) {
                s0 += sm_redA[g * 512 + en * 64 + eh];
                s1 += sm_redA[(g + 1) * 512 + en * 64 + eh];
            }
            float oA = tanhf(s0 + s1 + eb + pA);
            dst[(size_t)rowA * HID + h0 + eh] = oA;
            *selfA = oA;
            if (more) {
                int xa = __ldg(&X[rowA * LEN + t + 1]);
                pA = __ldg(&g_P[(size_t)xa * HID + h0 + eh]);
            }
        }
        __syncthreads();
        if (more && tid == 0)
            asm volatile("st.release.gpu.u32 [%0], %1;"
                         :: "l"(fA_my), "r"((unsigned)(t + 1)) : "memory");

        // ---- Phase 7-8: chain B compute --------------------------------
        if (!is_self)
            asm volatile("cp.async.wait_group 0;" ::: "memory");
        {
            u64 aA[8], aB[8];
#pragma unroll
            for (int n = 0; n < 8; n++) { aA[n] = 0ULL; aB[n] = 0ULL; }
            const float* hp = sm_hB + w * 256;
#pragma unroll
            for (int n = 0; n < 8; n++) {
                const float4* row = (const float4*)(hp + n * 32);
                u64 a0 = aA[n], a1 = aB[n];
#pragma unroll
                for (int j = 0; j < 8; j++) {
                    float4 hv = row[j];
                    u64 lo = ((const u64*)&hv)[0];
                    u64 hi = ((const u64*)&hv)[1];
                    a0 = ffma2(lo, wAr[2 * j],     a0);
                    a0 = ffma2(hi, wAr[2 * j + 1], a0);
                    a1 = ffma2(lo, wBr[2 * j],     a1);
                    a1 = ffma2(hi, wBr[2 * j + 1], a1);
                }
                aA[n] = a0; aB[n] = a1;
            }
#pragma unroll
            for (int n = 0; n < 8; n++) {
                float2 fa = *(float2*)&aA[n];
                float2 fb = *(float2*)&aB[n];
                *(float2*)&sm_redB[w * 512 + n * 64 + 2 * lane] =
                    make_float2(fa.x + fa.y, fb.x + fb.y);
            }
        }
        __syncthreads();

        // ---- Phase 9-11: reduce B, epilogue B, publish B ---------------
        {
            float s0 = 0.f, s1 = 0.f;
#pragma unroll
            for (int g = 0; g < 16; g += 2) {
                s0 += sm_redB[g * 512 + en * 64 + eh];
                s1 += sm_redB[(g + 1) * 512 + en * 64 + eh];
            }
            float oB = tanhf(s0 + s1 + eb + pB);
            dst[(size_t)rowB * HID + h0 + eh] = oB;
            *selfB = oB;
            if (more) {
                int xb = __ldg(&X[rowB * LEN + t + 1]);
                pB = __ldg(&g_P[(size_t)xb * HID + h0 + eh]);
            }
        }
        __syncthreads();
        if (more && tid == 0)
            asm volatile("st.release.gpu.u32 [%0], %1;"
                         :: "l"(fB_my), "r"((unsigned)(t + 1)) : "memory");

        // ---- Phase 13: chain A(t+1) poll + load ------------------------
        if (more && !is_self) {
            if (lane == 0) {
                unsigned g;
                do {
                    asm volatile("ld.acquire.gpu.u32 %0, [%1];"
                                 : "=r"(g) : "l"(fA_src) : "memory");
                } while (g < (unsigned)(t + 1));
            }
            __syncwarp();
            const float* hnow = g_h[t & 1];
#pragma unroll
            for (int i = 0; i < 2; i++) {
                int c = i * 32 + lane;
                const float* src = &hnow[(size_t)(n0A + (c >> 3)) * HID + w * 32 + (c & 7) * 4];
                asm volatile("cp.async.cg.shared.global [%0], [%1], 16;"
                             :: "r"(baseA + c * 16), "l"(src) : "memory");
            }
            asm volatile("cp.async.commit_group;" ::: "memory");
        }
    }

    // --- end-of-kernel cleanup: last CTA resets all flags + counter --------
    __syncthreads();
    if (tid == 0) {
        unsigned old;
        asm volatile("atom.acq_rel.gpu.global.add.u32 %0, [%1], %2;"
                     : "=r"(old) : "l"(&g_cnt[0]), "r"(1u) : "memory");
        if (old == GRID - 1) {
            for (int i = 0; i < NGRP * CL; i++)
                asm volatile("st.relaxed.gpu.u32 [%0], %1;"
                             :: "l"(&g_flag[i * 64]), "r"(0u) : "memory");
            asm volatile("st.relaxed.gpu.u32 [%0], %1;"
                         :: "l"(&g_cnt[0]), "r"(0u) : "memory");
        }
    }
}

// ---------------------------------------------------------------------------
extern "C" void kernel_launch(void* const* d_in, const int* in_sizes, int n_in,
                              void* d_out, int out_size) {
    const int*   X     = (const int*)d_in[0];
    const float* emb   = (const float*)d_in[1];
    const float* Whh_w = (const float*)d_in[2];
    const float* Whh_b = (const float*)d_in[3];
    const float* Wxh_w = (const float*)d_in[4];
    const float* Wxh_b = (const float*)d_in[5];
    float* out = (float*)d_out;

    const size_t sm_proj = (size_t)(64 * (EMB + 4) + 8 * 32 * 36) * sizeof(float); // ~101 KB
    const size_t sm_rnn  = (size_t)24576 * sizeof(float);                          // 96 KB
    cudaFuncSetAttribute(proj_kernel, cudaFuncAttributeMaxDynamicSharedMemorySize, (int)sm_proj);
    cudaFuncSetAttribute(rnn_kernel,  cudaFuncAttributeMaxDynamicSharedMemorySize, (int)sm_rnn);

    // 1) P = emb @ Wxh^T + Wxh_b
    proj_kernel<<<dim3(VOCAB / 32, HID / 32), 256, sm_proj>>>(emb, Wxh_w, Wxh_b);

    // 2) all 512 timesteps in one persistent dual-chain launch
    rnn_kernel<<<GRID, NTHR, sm_rnn>>>(X, Whh_w, Whh_b, out);
}

// round 15
// speedup vs baseline: 1.0425x; 1.0425x over previous
#include <cuda_runtime.h>
#include <cuda_bf16.h>
#include <stdint.h>
#include <math.h>

#define VOCAB 32000
#define HID   512
#define EMB   256
#define NB    256
#define LEN   512

#define CL    8            // h-tile CTAs per n-tile (flag group size)
#define NTILE 16           // n rows per block
#define HTILE 64           // h cols per block
#define NT    16           // number of n-tiles
#define GRID  128
#define NTHR  512

typedef unsigned long long u64;

// Scratch (static device allocations are allowed; runtime allocs are not).
__device__ float g_P[VOCAB * HID];            // P = emb @ Wxh^T + b  (65.5 MB)
__device__ float g_h[2][NB * HID];            // ping-pong hidden state
__device__ unsigned g_flag[NT * CL * 64];     // per-producer flags, 256B apart
__device__ unsigned g_cnt[NT * 64];           // end-of-kernel cleanup counters

// Packed fp32x2 ops (B300 packed pipe; ptxas never emits these from C++).
__device__ __forceinline__ u64 ffma2(u64 a, u64 b, u64 c) {
    u64 d;
    asm("fma.rn.f32x2 %0, %1, %2, %3;" : "=l"(d) : "l"(a), "l"(b), "l"(c));
    return d;
}
__device__ __forceinline__ u64 fadd2(u64 a, u64 b) {
    u64 d;
    asm("add.rn.f32x2 %0, %1, %2;" : "=l"(d) : "l"(a), "l"(b));
    return d;
}

// ---------------------------------------------------------------------------
// proj_kernel v3: g_P[v,h] = sum_e emb[v,e] * Wxh_w[h,e] + Wxh_b[h]
//   Mirrors the rnn compute core (the measured-efficient pattern):
//   64v x 64h tile per block, 256 threads = 8 k-groups x 32 lanes.
//   Lane owns h-pair (h0+2*lane, +1); its 32-k slice of W lives in REGISTERS
//   (32 u64) -> only the emb side touches SMEM, via broadcast LDS.128.
//   v processed in 8 chunks of 8 rows; k-group partials reduced through a
//   double-buffered SMEM buffer (one __syncthreads per chunk).
// ---------------------------------------------------------------------------
__global__ void __launch_bounds__(256, 2)
proj_kernel(const float* __restrict__ emb,
            const float* __restrict__ Wxh_w,
            const float* __restrict__ Wxh_b) {
    extern __shared__ float sm[];
    float*  As   = sm;                          // [64 v][256 k]  64 KB
    float2* red2 = (float2*)(sm + 64 * 256);    // 2 x [8 kg][8 v][32 l] 32 KB

    const int tid  = threadIdx.x;
    const int kg   = tid >> 5;                  // k-group 0..7
    const int lane = tid & 31;
    const int v0   = blockIdx.x * 64;
    const int h0   = blockIdx.y * 64;

    // --- weight registers: rows h0+2*lane, h0+2*lane+1, k in [32kg, 32kg+32)
    u64 wA[16], wB[16];
    {
        const u64* pa = (const u64*)&Wxh_w[(size_t)(h0 + 2 * lane) * EMB + kg * 32];
        const u64* pb = (const u64*)&Wxh_w[(size_t)(h0 + 2 * lane + 1) * EMB + kg * 32];
#pragma unroll
        for (int i = 0; i < 16; i++) { wA[i] = pa[i]; wB[i] = pb[i]; }
    }

    // --- load emb tile [64 v][256 k] (coalesced float4) ----------------------
    {
        const int r  = tid >> 2;
        const int cb = (tid & 3) * 64;
#pragma unroll
        for (int j = 0; j < 16; j++) {
            int c = cb + 4 * j;
            *(float4*)&As[r * 256 + c] =
                *(const float4*)&emb[(size_t)(v0 + r) * EMB + c];
        }
    }
    __syncthreads();

    // reduce-side ownership: thread (rv, rl) -> row rv of chunk, h-pair 2*rl
    const int    rv = tid >> 5;
    const int    rl = tid & 31;
    const float2 bv = *(const float2*)&Wxh_b[h0 + 2 * rl];

    // --- 8 v-chunks of 8 rows, double-buffered reduction ---------------------
#pragma unroll 1
    for (int c = 0; c < 8; c++) {
        float2* buf = red2 + (c & 1) * 2048;

        u64 aA[8], aB[8];
#pragma unroll
        for (int n = 0; n < 8; n++) { aA[n] = 0ULL; aB[n] = 0ULL; }
        const float* hp = As + (c * 8) * 256 + kg * 32;
#pragma unroll
        for (int n = 0; n < 8; n++) {
            const float4* row = (const float4*)(hp + n * 256);
            u64 a0 = aA[n], a1 = aB[n];
#pragma unroll
            for (int j = 0; j < 8; j++) {
                float4 hv = row[j];
                u64 lo = ((const u64*)&hv)[0];
                u64 hi = ((const u64*)&hv)[1];
                a0 = ffma2(lo, wA[2 * j],     a0);
                a0 = ffma2(hi, wA[2 * j + 1], a0);
                a1 = ffma2(lo, wB[2 * j],     a1);
                a1 = ffma2(hi, wB[2 * j + 1], a1);
            }
            aA[n] = a0; aB[n] = a1;
        }
#pragma unroll
        for (int n = 0; n < 8; n++) {
            float2 fa = *(float2*)&aA[n];
            float2 fb = *(float2*)&aB[n];
            buf[kg * 256 + n * 32 + lane] =
                make_float2(fa.x + fa.y, fb.x + fb.y);
        }
        __syncthreads();

        // reduce 8 k-groups, add bias, store float2.
        // WAR safety: chunk c+2 (same buffer) writes only after the
        // __syncthreads of chunk c+1, which all threads pass only after
        // finishing these reads.
        u64 s = 0ULL;
#pragma unroll
        for (int g = 0; g < 8; g++) {
            u64 v = *(const u64*)&buf[g * 256 + rv * 32 + rl];
            s = fadd2(s, v);
        }
        float2 rr = *(float2*)&s;
        rr.x += bv.x; rr.y += bv.y;
        *(float2*)&g_P[(size_t)(v0 + c * 8 + rv) * HID + h0 + 2 * rl] = rr;
    }
}

// ---------------------------------------------------------------------------
// rnn_kernel: ONE persistent launch, all 512 timesteps. NO clusters.
//   (R11 verbatim — the measured-best structure, 2833.7 us.)
//   128 CTAs = 16 n-tiles x 8 h-tiles, 16n x 64h per CTA.
//   Sync = per-PRODUCER flags: CTA j publishes flag[j]=t+1 after its step-t
//   epilogue; consumer warp w polls only flag[w>>1] (its sole producer), then
//   cp.asyncs its 16n x 32k slice (two commit groups; compute rows 0-7 under
//   rows 8-15's arrival). Own-CTA warps get their slice through SMEM written
//   by the epilogue and skip polling entirely.
// ---------------------------------------------------------------------------
__global__ void __launch_bounds__(NTHR, 1)
rnn_kernel(const int*   __restrict__ X,
           const float* __restrict__ Whh_w,
           const float* __restrict__ Whh_b,
           float*       __restrict__ out)
{
    extern __shared__ float sm[];
    float*  sm_h   = sm;                       // [16 w][16 n][32 k]   32 KB
    float2* sm_red = (float2*)(sm + 16 * 512); // [16 kg][16 n][32 l]  64 KB

    const int tid   = threadIdx.x;
    const int w     = tid >> 5;
    const int lane  = tid & 31;
    const int tile  = blockIdx.x >> 3;         // n-tile id (flag group)
    const int j_own = blockIdx.x & 7;          // own h-block id
    const int n0    = tile * NTILE;
    const int h0    = j_own * HTILE;
    const int hA    = h0 + 2 * lane;           // contiguous h pair
    const int hB    = hA + 1;

    const int  j_src   = w >> 1;               // producer this warp consumes
    const bool is_self = (j_src == j_own);

    // --- persistent weight registers: rows hA,hB, k in [32w, 32w+32) -------
    u64 wA[16], wB[16];
    {
        const u64* pa = (const u64*)&Whh_w[(size_t)hA * HID + w * 32];
        const u64* pb = (const u64*)&Whh_w[(size_t)hB * HID + w * 32];
#pragma unroll
        for (int i = 0; i < 16; i++) { wA[i] = pa[i]; wB[i] = pb[i]; }
    }

    unsigned int smem_w_base;
    {
        unsigned int a;
        asm("{ .reg .u64 t; cvta.to.shared.u64 t, %1; cvt.u32.u64 %0, t; }"
            : "=r"(a) : "l"(sm_h + w * 512));
        smem_w_base = a;
    }

    // epilogue ownership: thread (en, el) -> row n0+en, h-pair h0+2*el
    const int    en    = tid >> 5;
    const int    el    = tid & 31;
    const int    enab  = n0 + en;
    const float2 ebv   = *(const float2*)&Whh_b[h0 + 2 * el];
    // SMEM destination for own slice: warp 2*j_own + (el>=16), [n=en][kk=2el&31]
    float* sm_self = &sm_h[(2 * j_own + (el >> 4)) * 512 + en * 32 + ((2 * el) & 31)];

    unsigned* my_flag  = &g_flag[(tile * CL + j_own) * 64];
    unsigned* src_flag = &g_flag[(tile * CL + j_src) * 64];

    // preload step-0 gather
    float2 pv;
    {
        int xid = __ldg(&X[enab * LEN]);
        pv = __ldg((const float2*)&g_P[(size_t)xid * HID + h0 + 2 * el]);
    }

    for (int t = 0; t < LEN; t++) {
        float* dst = (t == LEN - 1) ? out : ((t & 1) ? g_h[1] : g_h[0]);
        const float* hin = (t & 1) ? g_h[0] : g_h[1];

        float sA = 0.f, sB = 0.f;

        if (t > 0) {
            if (!is_self) {
                // --- wait for our single producer -----------------------------
                if (lane == 0) {
                    unsigned g;
                    do {
                        asm volatile("ld.acquire.gpu.u32 %0, [%1];"
                                     : "=r"(g) : "l"(src_flag) : "memory");
                    } while (g < (unsigned)t);
                }
                __syncwarp();
                // --- pull its slice in TWO commit groups (rows 0-7, 8-15) ----
#pragma unroll
                for (int half = 0; half < 2; half++) {
#pragma unroll
                    for (int i = 0; i < 2; i++) {
                        int c  = half * 64 + i * 32 + lane;  // 16B chunk (0..127)
                        int n  = c >> 3;
                        int kq = c & 7;
                        const float* src =
                            &hin[(size_t)(n0 + n) * HID + w * 32 + kq * 4];
                        asm volatile("cp.async.cg.shared.global [%0], [%1], 16;"
                                     :: "r"(smem_w_base + c * 16), "l"(src)
                                     : "memory");
                    }
                    asm volatile("cp.async.commit_group;" ::: "memory");
                }
            }
            // (self warps: slice already in SMEM from last step's epilogue)

            // --- compute in two n-halves of 8; half 0 under half 1's arrival
#pragma unroll
            for (int half = 0; half < 2; half++) {
                if (!is_self) {
                    if (half == 0)
                        asm volatile("cp.async.wait_group 1;" ::: "memory");
                    else
                        asm volatile("cp.async.wait_group 0;" ::: "memory");
                }
                u64 aA[8], aB[8];
#pragma unroll
                for (int n = 0; n < 8; n++) { aA[n] = 0ULL; aB[n] = 0ULL; }
                const float* hp = sm_h + w * 512 + half * 8 * 32;
#pragma unroll
                for (int n = 0; n < 8; n++) {
                    const float4* row = (const float4*)(hp + n * 32);
                    u64 a0 = aA[n], a1 = aB[n];
#pragma unroll
                    for (int j = 0; j < 8; j++) {
                        float4 hv = row[j];
                        u64 lo = ((const u64*)&hv)[0];
                        u64 hi = ((const u64*)&hv)[1];
                        a0 = ffma2(lo, wA[2 * j],     a0);
                        a0 = ffma2(hi, wA[2 * j + 1], a0);
                        a1 = ffma2(lo, wB[2 * j],     a1);
                        a1 = ffma2(hi, wB[2 * j + 1], a1);
                    }
                    aA[n] = a0; aB[n] = a1;
                }
#pragma unroll
                for (int n = 0; n < 8; n++) {
                    float2 fa = *(float2*)&aA[n];
                    float2 fb = *(float2*)&aB[n];
                    sm_red[w * 512 + (half * 8 + n) * 32 + lane] =
                        make_float2(fa.x + fa.y, fb.x + fb.y);
                }
            }
            __syncthreads();

            // --- k-group reduction, packed f32x2 ------------------------------
            u64 r1 = 0ULL, r2 = 0ULL;
#pragma unroll
            for (int g = 0; g < 16; g += 2) {
                u64 v0 = *(const u64*)&sm_red[g * 512 + tid];
                u64 v1 = *(const u64*)&sm_red[(g + 1) * 512 + tid];
                r1 = fadd2(r1, v0);
                r2 = fadd2(r2, v1);
            }
            u64 rt = fadd2(r1, r2);
            float2 rr = *(float2*)&rt;
            sA = rr.x; sB = rr.y;
        }

        // --- fused epilogue: bias + P + tanh; publish to GMEM + own SMEM -----
        float2 o;
        o.x = tanhf(sA + ebv.x + pv.x);
        o.y = tanhf(sB + ebv.y + pv.y);
        *(float2*)&dst[(size_t)enab * HID + h0 + 2 * el] = o;
        *(float2*)sm_self = o;                 // self-warps read this next step

        if (t < LEN - 1) {
            // prefetch next step's gather (g_P immutable; hides under publish)
            int xid2 = __ldg(&X[enab * LEN + t + 1]);
            pv = __ldg((const float2*)&g_P[(size_t)xid2 * HID + h0 + 2 * el]);

            __syncthreads();                   // epilogue stores + STS done
            if (tid == 0) {
                asm volatile("st.release.gpu.u32 [%0], %1;"
                             :: "l"(my_flag), "r"((unsigned)(t + 1)) : "memory");
            }
        }
    }

    // --- end-of-kernel cleanup: last CTA of the group resets flags/counter --
    __syncthreads();
    if (tid == 0) {
        unsigned old;
        asm volatile("atom.acq_rel.gpu.global.add.u32 %0, [%1], %2;"
                     : "=r"(old) : "l"(&g_cnt[tile * 64]), "r"(1u) : "memory");
        if (old == CL - 1) {
#pragma unroll
            for (int j = 0; j < CL; j++)
                asm volatile("st.relaxed.gpu.u32 [%0], %1;"
                             :: "l"(&g_flag[(tile * CL + j) * 64]), "r"(0u)
                             : "memory");
            asm volatile("st.relaxed.gpu.u32 [%0], %1;"
                         :: "l"(&g_cnt[tile * 64]), "r"(0u) : "memory");
        }
    }
}

// ---------------------------------------------------------------------------
extern "C" void kernel_launch(void* const* d_in, const int* in_sizes, int n_in,
                              void* d_out, int out_size) {
    const int*   X     = (const int*)d_in[0];
    const float* emb   = (const float*)d_in[1];
    const float* Whh_w = (const float*)d_in[2];
    const float* Whh_b = (const float*)d_in[3];
    const float* Wxh_w = (const float*)d_in[4];
    const float* Wxh_b = (const float*)d_in[5];
    float* out = (float*)d_out;

    const size_t sm_proj = (size_t)(64 * 256 + 2 * 2048 * 2) * sizeof(float);  // 96 KB
    const size_t sm_rnn  = (size_t)(16 * 512) * sizeof(float)                  // 32 KB h
                         + (size_t)(16 * 512) * sizeof(float2);                // 64 KB red
    cudaFuncSetAttribute(proj_kernel, cudaFuncAttributeMaxDynamicSharedMemorySize, (int)sm_proj);
    cudaFuncSetAttribute(rnn_kernel,  cudaFuncAttributeMaxDynamicSharedMemorySize, (int)sm_rnn);

    // 1) P = emb @ Wxh^T + Wxh_b   (64v x 64h tiles, weights in registers)
    proj_kernel<<<dim3(VOCAB / 64, HID / 64), 256, sm_proj>>>(emb, Wxh_w, Wxh_b);

    // 2) all 512 timesteps in one persistent launch
    rnn_kernel<<<GRID, NTHR, sm_rnn>>>(X, Whh_w, Whh_b, out);
}

// round 16
// speedup vs baseline: 1.0434x; 1.0009x over previous
#include <cuda_runtime.h>
#include <cuda_bf16.h>
#include <stdint.h>
#include <math.h>

#define VOCAB 32000
#define HID   512
#define EMB   256
#define NB    256
#define LEN   512

#define CL    8            // h-tile CTAs per n-tile (flag group size)
#define NTILE 16           // n rows per block
#define HTILE 64           // h cols per block
#define NT    16           // number of n-tiles
#define GRID  128
#define NTHR  512

typedef unsigned long long u64;

// Scratch (static device allocations are allowed; runtime allocs are not).
__device__ float g_P[VOCAB * HID];            // P = emb @ Wxh^T + b  (65.5 MB)
__device__ float g_h[2][NB * HID];            // ping-pong hidden state
__device__ unsigned g_flag[NT * CL * 64];     // per-producer flags, 256B apart
__device__ unsigned g_cnt[NT * 64];           // end-of-kernel cleanup counters

// Packed fp32x2 ops (B300 packed pipe; ptxas never emits these from C++).
__device__ __forceinline__ u64 ffma2(u64 a, u64 b, u64 c) {
    u64 d;
    asm("fma.rn.f32x2 %0, %1, %2, %3;" : "=l"(d) : "l"(a), "l"(b), "l"(c));
    return d;
}
__device__ __forceinline__ u64 fadd2(u64 a, u64 b) {
    u64 d;
    asm("add.rn.f32x2 %0, %1, %2;" : "=l"(d) : "l"(a), "l"(b));
    return d;
}

// ---------------------------------------------------------------------------
// proj_kernel v3: g_P[v,h] = sum_e emb[v,e] * Wxh_w[h,e] + Wxh_b[h]
//   Mirrors the rnn compute core (the measured-efficient pattern):
//   64v x 64h tile per block, 256 threads = 8 k-groups x 32 lanes.
//   Lane owns h-pair (h0+2*lane, +1); its 32-k slice of W lives in REGISTERS
//   (32 u64) -> only the emb side touches SMEM, via broadcast LDS.128.
//   v processed in 8 chunks of 8 rows; k-group partials reduced through a
//   double-buffered SMEM buffer (one __syncthreads per chunk).
// ---------------------------------------------------------------------------
__global__ void __launch_bounds__(256, 2)
proj_kernel(const float* __restrict__ emb,
            const float* __restrict__ Wxh_w,
            const float* __restrict__ Wxh_b) {
    extern __shared__ float sm[];
    float*  As   = sm;                          // [64 v][256 k]  64 KB
    float2* red2 = (float2*)(sm + 64 * 256);    // 2 x [8 kg][8 v][32 l] 32 KB

    const int tid  = threadIdx.x;
    const int kg   = tid >> 5;                  // k-group 0..7
    const int lane = tid & 31;
    const int v0   = blockIdx.x * 64;
    const int h0   = blockIdx.y * 64;

    // --- weight registers: rows h0+2*lane, h0+2*lane+1, k in [32kg, 32kg+32)
    u64 wA[16], wB[16];
    {
        const u64* pa = (const u64*)&Wxh_w[(size_t)(h0 + 2 * lane) * EMB + kg * 32];
        const u64* pb = (const u64*)&Wxh_w[(size_t)(h0 + 2 * lane + 1) * EMB + kg * 32];
#pragma unroll
        for (int i = 0; i < 16; i++) { wA[i] = pa[i]; wB[i] = pb[i]; }
    }

    // --- load emb tile [64 v][256 k] (coalesced float4) ----------------------
    {
        const int r  = tid >> 2;
        const int cb = (tid & 3) * 64;
#pragma unroll
        for (int j = 0; j < 16; j++) {
            int c = cb + 4 * j;
            *(float4*)&As[r * 256 + c] =
                *(const float4*)&emb[(size_t)(v0 + r) * EMB + c];
        }
    }
    __syncthreads();

    // reduce-side ownership: thread (rv, rl) -> row rv of chunk, h-pair 2*rl
    const int    rv = tid >> 5;
    const int    rl = tid & 31;
    const float2 bv = *(const float2*)&Wxh_b[h0 + 2 * rl];

    // --- 8 v-chunks of 8 rows, double-buffered reduction ---------------------
#pragma unroll 1
    for (int c = 0; c < 8; c++) {
        float2* buf = red2 + (c & 1) * 2048;

        u64 aA[8], aB[8];
#pragma unroll
        for (int n = 0; n < 8; n++) { aA[n] = 0ULL; aB[n] = 0ULL; }
        const float* hp = As + (c * 8) * 256 + kg * 32;
#pragma unroll
        for (int n = 0; n < 8; n++) {
            const float4* row = (const float4*)(hp + n * 256);
            u64 a0 = aA[n], a1 = aB[n];
#pragma unroll
            for (int j = 0; j < 8; j++) {
                float4 hv = row[j];
                u64 lo = ((const u64*)&hv)[0];
                u64 hi = ((const u64*)&hv)[1];
                a0 = ffma2(lo, wA[2 * j],     a0);
                a0 = ffma2(hi, wA[2 * j + 1], a0);
                a1 = ffma2(lo, wB[2 * j],     a1);
                a1 = ffma2(hi, wB[2 * j + 1], a1);
            }
            aA[n] = a0; aB[n] = a1;
        }
#pragma unroll
        for (int n = 0; n < 8; n++) {
            float2 fa = *(float2*)&aA[n];
            float2 fb = *(float2*)&aB[n];
            buf[kg * 256 + n * 32 + lane] =
                make_float2(fa.x + fa.y, fb.x + fb.y);
        }
        __syncthreads();

        // reduce 8 k-groups, add bias, store float2.
        // WAR safety: chunk c+2 (same buffer) writes only after the
        // __syncthreads of chunk c+1, which all threads pass only after
        // finishing these reads.
        u64 s = 0ULL;
#pragma unroll
        for (int g = 0; g < 8; g++) {
            u64 v = *(const u64*)&buf[g * 256 + rv * 32 + rl];
            s = fadd2(s, v);
        }
        float2 rr = *(float2*)&s;
        rr.x += bv.x; rr.y += bv.y;
        *(float2*)&g_P[(size_t)(v0 + c * 8 + rv) * HID + h0 + 2 * rl] = rr;
    }
}

// ---------------------------------------------------------------------------
// rnn_kernel: ONE persistent launch, all 512 timesteps. NO clusters.
//   (R11 verbatim — the measured-best structure, 2833.7 us.)
//   128 CTAs = 16 n-tiles x 8 h-tiles, 16n x 64h per CTA.
//   Sync = per-PRODUCER flags: CTA j publishes flag[j]=t+1 after its step-t
//   epilogue; consumer warp w polls only flag[w>>1] (its sole producer), then
//   cp.asyncs its 16n x 32k slice (two commit groups; compute rows 0-7 under
//   rows 8-15's arrival). Own-CTA warps get their slice through SMEM written
//   by the epilogue and skip polling entirely.
// ---------------------------------------------------------------------------
__global__ void __launch_bounds__(NTHR, 1)
rnn_kernel(const int*   __restrict__ X,
           const float* __restrict__ Whh_w,
           const float* __restrict__ Whh_b,
           float*       __restrict__ out)
{
    extern __shared__ float sm[];
    float*  sm_h   = sm;                       // [16 w][16 n][32 k]   32 KB
    float2* sm_red = (float2*)(sm + 16 * 512); // [16 kg][16 n][32 l]  64 KB

    const int tid   = threadIdx.x;
    const int w     = tid >> 5;
    const int lane  = tid & 31;
    const int tile  = blockIdx.x >> 3;         // n-tile id (flag group)
    const int j_own = blockIdx.x & 7;          // own h-block id
    const int n0    = tile * NTILE;
    const int h0    = j_own * HTILE;
    const int hA    = h0 + 2 * lane;           // contiguous h pair
    const int hB    = hA + 1;

    const int  j_src   = w >> 1;               // producer this warp consumes
    const bool is_self = (j_src == j_own);

    // --- persistent weight registers: rows hA,hB, k in [32w, 32w+32) -------
    u64 wA[16], wB[16];
    {
        const u64* pa = (const u64*)&Whh_w[(size_t)hA * HID + w * 32];
        const u64* pb = (const u64*)&Whh_w[(size_t)hB * HID + w * 32];
#pragma unroll
        for (int i = 0; i < 16; i++) { wA[i] = pa[i]; wB[i] = pb[i]; }
    }

    unsigned int smem_w_base;
    {
        unsigned int a;
        asm("{ .reg .u64 t; cvta.to.shared.u64 t, %1; cvt.u32.u64 %0, t; }"
            : "=r"(a) : "l"(sm_h + w * 512));
        smem_w_base = a;
    }

    // epilogue ownership: thread (en, el) -> row n0+en, h-pair h0+2*el
    const int    en    = tid >> 5;
    const int    el    = tid & 31;
    const int    enab  = n0 + en;
    const float2 ebv   = *(const float2*)&Whh_b[h0 + 2 * el];
    // SMEM destination for own slice: warp 2*j_own + (el>=16), [n=en][kk=2el&31]
    float* sm_self = &sm_h[(2 * j_own + (el >> 4)) * 512 + en * 32 + ((2 * el) & 31)];

    unsigned* my_flag  = &g_flag[(tile * CL + j_own) * 64];
    unsigned* src_flag = &g_flag[(tile * CL + j_src) * 64];

    // preload step-0 gather
    float2 pv;
    {
        int xid = __ldg(&X[enab * LEN]);
        pv = __ldg((const float2*)&g_P[(size_t)xid * HID + h0 + 2 * el]);
    }

    for (int t = 0; t < LEN; t++) {
        float* dst = (t == LEN - 1) ? out : ((t & 1) ? g_h[1] : g_h[0]);
        const float* hin = (t & 1) ? g_h[0] : g_h[1];

        float sA = 0.f, sB = 0.f;

        if (t > 0) {
            if (!is_self) {
                // --- wait for our single producer -----------------------------
                if (lane == 0) {
                    unsigned g;
                    do {
                        asm volatile("ld.acquire.gpu.u32 %0, [%1];"
                                     : "=r"(g) : "l"(src_flag) : "memory");
                    } while (g < (unsigned)t);
                }
                __syncwarp();
                // --- pull its slice in TWO commit groups (rows 0-7, 8-15) ----
#pragma unroll
                for (int half = 0; half < 2; half++) {
#pragma unroll
                    for (int i = 0; i < 2; i++) {
                        int c  = half * 64 + i * 32 + lane;  // 16B chunk (0..127)
                        int n  = c >> 3;
                        int kq = c & 7;
                        const float* src =
                            &hin[(size_t)(n0 + n) * HID + w * 32 + kq * 4];
                        asm volatile("cp.async.cg.shared.global [%0], [%1], 16;"
                                     :: "r"(smem_w_base + c * 16), "l"(src)
                                     : "memory");
                    }
                    asm volatile("cp.async.commit_group;" ::: "memory");
                }
            }
            // (self warps: slice already in SMEM from last step's epilogue)

            // --- compute in two n-halves of 8; half 0 under half 1's arrival
#pragma unroll
            for (int half = 0; half < 2; half++) {
                if (!is_self) {
                    if (half == 0)
                        asm volatile("cp.async.wait_group 1;" ::: "memory");
                    else
                        asm volatile("cp.async.wait_group 0;" ::: "memory");
                }
                u64 aA[8], aB[8];
#pragma unroll
                for (int n = 0; n < 8; n++) { aA[n] = 0ULL; aB[n] = 0ULL; }
                const float* hp = sm_h + w * 512 + half * 8 * 32;
#pragma unroll
                for (int n = 0; n < 8; n++) {
                    const float4* row = (const float4*)(hp + n * 32);
                    u64 a0 = aA[n], a1 = aB[n];
#pragma unroll
                    for (int j = 0; j < 8; j++) {
                        float4 hv = row[j];
                        u64 lo = ((const u64*)&hv)[0];
                        u64 hi = ((const u64*)&hv)[1];
                        a0 = ffma2(lo, wA[2 * j],     a0);
                        a0 = ffma2(hi, wA[2 * j + 1], a0);
                        a1 = ffma2(lo, wB[2 * j],     a1);
                        a1 = ffma2(hi, wB[2 * j + 1], a1);
                    }
                    aA[n] = a0; aB[n] = a1;
                }
#pragma unroll
                for (int n = 0; n < 8; n++) {
                    float2 fa = *(float2*)&aA[n];
                    float2 fb = *(float2*)&aB[n];
                    sm_red[w * 512 + (half * 8 + n) * 32 + lane] =
                        make_float2(fa.x + fa.y, fb.x + fb.y);
                }
            }
            __syncthreads();

            // --- k-group reduction, packed f32x2 ------------------------------
            u64 r1 = 0ULL, r2 = 0ULL;
#pragma unroll
            for (int g = 0; g < 16; g += 2) {
                u64 v0 = *(const u64*)&sm_red[g * 512 + tid];
                u64 v1 = *(const u64*)&sm_red[(g + 1) * 512 + tid];
                r1 = fadd2(r1, v0);
                r2 = fadd2(r2, v1);
            }
            u64 rt = fadd2(r1, r2);
            float2 rr = *(float2*)&rt;
            sA = rr.x; sB = rr.y;
        }

        // --- fused epilogue: bias + P + tanh; publish to GMEM + own SMEM -----
        float2 o;
        o.x = tanhf(sA + ebv.x + pv.x);
        o.y = tanhf(sB + ebv.y + pv.y);
        *(float2*)&dst[(size_t)enab * HID + h0 + 2 * el] = o;
        *(float2*)sm_self = o;                 // self-warps read this next step

        if (t < LEN - 1) {
            // prefetch next step's gather (g_P immutable; hides under publish)
            int xid2 = __ldg(&X[enab * LEN + t + 1]);
            pv = __ldg((const float2*)&g_P[(size_t)xid2 * HID + h0 + 2 * el]);

            __syncthreads();                   // epilogue stores + STS done
            if (tid == 0) {
                asm volatile("st.release.gpu.u32 [%0], %1;"
                             :: "l"(my_flag), "r"((unsigned)(t + 1)) : "memory");
            }
        }
    }

    // --- end-of-kernel cleanup: last CTA of the group resets flags/counter --
    __syncthreads();
    if (tid == 0) {
        unsigned old;
        asm volatile("atom.acq_rel.gpu.global.add.u32 %0, [%1], %2;"
                     : "=r"(old) : "l"(&g_cnt[tile * 64]), "r"(1u) : "memory");
        if (old == CL - 1) {
#pragma unroll
            for (int j = 0; j < CL; j++)
                asm volatile("st.relaxed.gpu.u32 [%0], %1;"
                             :: "l"(&g_flag[(tile * CL + j) * 64]), "r"(0u)
                             : "memory");
            asm volatile("st.relaxed.gpu.u32 [%0], %1;"
                         :: "l"(&g_cnt[tile * 64]), "r"(0u) : "memory");
        }
    }
}

// ---------------------------------------------------------------------------
extern "C" void kernel_launch(void* const* d_in, const int* in_sizes, int n_in,
                              void* d_out, int out_size) {
    const int*   X     = (const int*)d_in[0];
    const float* emb   = (const float*)d_in[1];
    const float* Whh_w = (const float*)d_in[2];
    const float* Whh_b = (const float*)d_in[3];
    const float* Wxh_w = (const float*)d_in[4];
    const float* Wxh_b = (const float*)d_in[5];
    float* out = (float*)d_out;

    const size_t sm_proj = (size_t)(64 * 256 + 2 * 2048 * 2) * sizeof(float);  // 96 KB
    const size_t sm_rnn  = (size_t)(16 * 512) * sizeof(float)                  // 32 KB h
                         + (size_t)(16 * 512) * sizeof(float2);                // 64 KB red
    cudaFuncSetAttribute(proj_kernel, cudaFuncAttributeMaxDynamicSharedMemorySize, (int)sm_proj);
    cudaFuncSetAttribute(rnn_kernel,  cudaFuncAttributeMaxDynamicSharedMemorySize, (int)sm_rnn);

    // 1) P = emb @ Wxh^T + Wxh_b   (64v x 64h tiles, weights in registers)
    proj_kernel<<<dim3(VOCAB / 64, HID / 64), 256, sm_proj>>>(emb, Wxh_w, Wxh_b);

    // 2) all 512 timesteps in one persistent launch
    rnn_kernel<<<GRID, NTHR, sm_rnn>>>(X, Whh_w, Whh_b, out);
}